// round 1
// baseline (speedup 1.0000x reference)
#include <cuda_runtime.h>
#include <cstdint>

#define TSTEPS   2048
#define NREACH   16383
#define DEPTH    8
#define NCTA     134
#define SENTINEL 0xFFFFFFFFu

#define DT_SUB_F  21600.0f
#define EPS_F     1e-6f
#define LOG2EPS_F  (-19.931568569324174f)
#define NLOG2EPS_F ( 19.931568569324174f)
#define C23_F      0.66666666666666667f

// Ring buffers: per producer CTA, DEPTH slots of up to 64 pair-sums.
__device__ unsigned g_qbuf[NCTA][DEPTH][64];

static __device__ __forceinline__ unsigned ld_rlx(const unsigned* p) {
    unsigned v;
    asm volatile("ld.relaxed.gpu.global.b32 %0, [%1];" : "=r"(v) : "l"(p) : "memory");
    return v;
}
static __device__ __forceinline__ void st_rlx(unsigned* p, unsigned v) {
    asm volatile("st.relaxed.gpu.global.b32 [%0], %1;" :: "l"(p), "r"(v) : "memory");
}
static __device__ __forceinline__ float ex2f_(float x){ float y; asm("ex2.approx.f32 %0, %1;" : "=f"(y) : "f"(x)); return y; }
static __device__ __forceinline__ float lg2f_(float x){ float y; asm("lg2.approx.f32 %0, %1;" : "=f"(y) : "f"(x)); return y; }
static __device__ __forceinline__ float rcpf_(float x){ float y; asm("rcp.approx.f32 %0, %1;" : "=f"(y) : "f"(x)); return y; }

__global__ void init_bufs() {
    int i = blockIdx.x * blockDim.x + threadIdx.x;
    if (i < NCTA * DEPTH * 64) ((unsigned*)g_qbuf)[i] = SENTINEL;
}

__global__ void __launch_bounds__(128, 1) route_kernel(
    const float* __restrict__ lat,
    const float* __restrict__ logn,
    const float* __restrict__ lens,
    const float* __restrict__ slp,
    const float* __restrict__ wcs,
    const float* __restrict__ wes,
    const float* __restrict__ dcs,
    const float* __restrict__ des,
    float* __restrict__ out)
{
    const int b = blockIdx.x, tid = threadIdx.x;

    // Decode (level, chunk) from block id.
    int l, m;
    if      (b < 64)  { l = 0;  m = b; }
    else if (b < 96)  { l = 1;  m = b - 64; }
    else if (b < 112) { l = 2;  m = b - 96; }
    else if (b < 120) { l = 3;  m = b - 112; }
    else if (b < 124) { l = 4;  m = b - 120; }
    else if (b < 126) { l = 5;  m = b - 124; }
    else if (b == 126){ l = 6;  m = 0; }
    else              { l = b - 120; m = 0; }   // 127..133 -> levels 7..13

    const int sl = 8192 >> l;
    const int active = sl < 128 ? sl : 128;
    if (tid >= active) return;                   // idle threads exit (sm_70+ barrier-safe; no CTA barriers used anyway)

    const int Ol = 16384 - (16384 >> l);         // level offset in reach space
    const int r  = Ol + 128 * m + tid;           // my reach

    const bool is_outlet = (l == 13);
    const bool writer = (!is_outlet) && ((tid & 1) == 0);
    const unsigned shmask = (active >= 32) ? 0xFFFFFFFFu : ((1u << active) - 1u);

    // Producer element I consume (levels > 0): pair-sum index == my level-local index.
    const unsigned* consume_base = nullptr;
    if (l > 0) {
        const int jl = 128 * m + tid;
        const int sp = 8192 >> (l - 1);
        const int pc = (sp >= 128) ? 64 : (sp >> 1);                       // pair-sums per producer CTA
        const int pb = ((l - 1) <= 6) ? (128 - (128 >> (l - 1))) : (120 + (l - 1)); // producer level's CTA base
        consume_base = &g_qbuf[pb + jl / pc][0][jl % pc];
    }
    unsigned* write_base = writer ? &g_qbuf[b][0][tid >> 1] : nullptr;

    // Per-reach time-invariant constants (one-time, accurate paths).
    const float n_man = __expf(logn[r]);
    const float dx    = lens[r];
    const float S     = slp[r];
    const float we    = wes[r];
    const float nlwc  = -__log2f(wcs[r]);                 // -log2(width_coef)
    const float de    = des[r];
    const float ldc   = __log2f(dcs[r]);                  //  log2(depth_coef)
    const float sSn   = sqrtf(S) / n_man;
    const float nbasec = -__log2f(1.66666666667f * sSn);  // -log2(5/3 * sqrt(S)/n)
    const float inv2Sdx = 1.0f / (2.0f * S * dx);
    const float dx2   = 2.0f * dx;

    float Q = 0.0f, Iprev = 0.0f;
    const float* latp = lat + r;
    float lat_cur = __ldg(latp);                 // t = 0

    for (int t = 0; t < TSTEPS; ++t) {
        const int slot = t & (DEPTH - 1);

        // Prefetch next timestep's lateral inflow (hides DRAM latency behind compute).
        float lat_next = 0.0f;
        if (t + 1 < TSTEPS) lat_next = __ldg(latp + (size_t)(t + 1) * NREACH);

        // Early-issue both handshake loads; complete the free-wait only at the end.
        unsigned* wp = writer ? (write_base + slot * 64) : nullptr;
        unsigned vfree = SENTINEL;
        if (writer) vfree = ld_rlx(wp);

        float Inew = lat_cur;
        if (l > 0) {
            const unsigned* cp = consume_base + slot * 64;
            unsigned v = ld_rlx(cp);
            while (v == SENTINEL) { __nanosleep(40); v = ld_rlx(cp); }
            st_rlx((unsigned*)cp, SENTINEL);     // ack: slot element is free again
            Inew += __uint_as_float(v);
        }

        // 4 Muskingum-Cunge substeps (log2-domain fast-path, 4 MUFU each).
        float q = Q, io = Iprev;
        #pragma unroll
        for (int s = 0; s < 4; ++s) {
            const float Qref = fmaxf((Inew + io + q) * (1.0f / 3.0f), EPS_F);
            const float lq   = lg2f_(Qref);
            const float nlw  = fminf(fmaf(-we, lq, nlwc), NLOG2EPS_F);   // -log2(max(width,EPS))
            const float rw   = ex2f_(nlw);                               // 1/width
            const float tc   = fmaxf(fmaf(de, lq, ldc), LOG2EPS_F);      // log2(max(depth,EPS))
            const float nlc  = fminf(fmaf(-C23_F, tc, nbasec), NLOG2EPS_F); // -log2(max(c,EPS))
            const float rc   = ex2f_(nlc);                               // 1/c
            const float K2   = dx2 * rc;                                 // 2K
            float X = fmaf(-(Qref * rc) * rw, inv2Sdx, 0.5f);
            X = fminf(fmaxf(X, 0.0f), 0.5f);
            const float A  = K2 * X;                                     // 2KX
            const float B  = K2 - A;                                     // 2K(1-X)
            const float Dd = B + DT_SUB_F;
            const float rD = rcpf_(Dd);
            float acc = (DT_SUB_F - A) * Inew;
            acc = fmaf(DT_SUB_F + A, io, acc);
            acc = fmaf(B - DT_SUB_F, q, acc);
            q = fmaxf(acc * rD, 0.0f);
            io = Inew;
        }
        Q = q; Iprev = Inew;

        if (!is_outlet) {
            // Pair-sum for the downstream level; even lanes publish.
            const float ps = q + __shfl_xor_sync(shmask, q, 1);
            if (writer) {
                while (vfree != SENTINEL) { __nanosleep(40); vfree = ld_rlx(wp); }
                st_rlx(wp, __float_as_uint(ps));
            }
        } else {
            out[t] = q;    // single outlet thread
        }
        lat_cur = lat_next;
    }
}

extern "C" void kernel_launch(void* const* d_in, const int* in_sizes, int n_in,
                              void* d_out, int out_size) {
    const float* lat  = (const float*)d_in[0];
    const float* logn = (const float*)d_in[1];
    const float* lens = (const float*)d_in[2];
    const float* slp  = (const float*)d_in[3];
    const float* wcs  = (const float*)d_in[4];
    const float* wes  = (const float*)d_in[5];
    const float* dcs  = (const float*)d_in[6];
    const float* des  = (const float*)d_in[7];
    float* out = (float*)d_out;

    init_bufs<<<(NCTA * DEPTH * 64 + 255) / 256, 256>>>();
    route_kernel<<<NCTA, 128>>>(lat, logn, lens, slp, wcs, wes, dcs, des, out);
}

// round 4
// speedup vs baseline: 1.0176x; 1.0176x over previous
#include <cuda_runtime.h>

#define TSTEPS   2048
#define NREACH   16383
#define DEPTH    16
#define SENT     0xFFFFFFFFu
#define DT_SUB_F 21600.0f
#define EPS_F    1e-6f

// Ring: subtree-root (level 7, 64 elements) -> top CTA (level 8). 64*16 words.
__device__ unsigned g_ring[64][DEPTH];

static __device__ __forceinline__ unsigned ld_rlx(const unsigned* p) {
    unsigned v;
    asm volatile("ld.relaxed.gpu.global.b32 %0, [%1];" : "=r"(v) : "l"(p) : "memory");
    return v;
}
static __device__ __forceinline__ void st_rlx(unsigned* p, unsigned v) {
    asm volatile("st.relaxed.gpu.global.b32 [%0], %1;" :: "l"(p), "r"(v) : "memory");
}
static __device__ __forceinline__ float ex2f_(float x){ float y; asm("ex2.approx.f32 %0, %1;" : "=f"(y) : "f"(x)); return y; }
static __device__ __forceinline__ float lg2f_(float x){ float y; asm("lg2.approx.f32 %0, %1;" : "=f"(y) : "f"(x)); return y; }
static __device__ __forceinline__ float rcpf_(float x){ float y; asm("rcp.approx.f32 %0, %1;" : "=f"(y) : "f"(x)); return y; }

__global__ void init_ring() {
    int i = blockIdx.x * blockDim.x + threadIdx.x;
    if (i < 64 * DEPTH) ((unsigned*)g_ring)[i] = SENT;
}

__global__ void __launch_bounds__(256, 1) route_kernel(
    const float* __restrict__ lat,
    const float* __restrict__ logn,
    const float* __restrict__ lens,
    const float* __restrict__ slp,
    const float* __restrict__ wcs,
    const float* __restrict__ wes,
    const float* __restrict__ dcs,
    const float* __restrict__ des,
    float* __restrict__ out)
{
    __shared__ float sq[2][256];

    const int b   = blockIdx.x;
    const int tid = threadIdx.x;
    const bool top = (b == 64);

    // ---- decode (level, element) ----
    int  j = 0, r = 0, skew = 0, cbase = 0;
    bool active = false, has_par = false, is_root = false, is_outlet = false, is_l8 = false;

    if (!top) {
        if (tid != 255) {
            const int u = 255 - tid;              // 1..255
            const int l = __clz(u) - 24;          // level 0..7 within subtree
            j = tid - (256 - (256 >> l));         // local element in level
            r = (16384 - (16384 >> l)) + b * (128 >> l) + j;
            skew    = l;
            active  = true;
            has_par = (l > 0);
            cbase   = (l > 0) ? (256 - (256 >> (l - 1))) : 0;
            is_root = (tid == 254);               // level-7 root of subtree
        }
    } else {
        if (tid < 63) {
            const int u  = 63 - tid;              // 1..63
            const int ll = __clz(u) - 26;         // 0..5 -> global level 8..13
            j = tid - (64 - (64 >> ll));
            const int lg = 8 + ll;
            r = (16384 - (16384 >> lg)) + j;
            skew    = ll;
            active  = true;
            has_par = (ll > 0);
            cbase   = (ll > 0) ? (64 - (64 >> (ll - 1))) : 0;
            is_l8   = (ll == 0);
            is_outlet = (ll == 5);
        }
    }

    // ---- per-reach constants (accurate one-time math) ----
    float negCE = 0.f, kd = 0.f, xc = 0.f, xd = 0.f;
    const float* latp = lat;
    float lat_c = 0.f, lat_n = 0.f;
    float Q = 0.f, Ip = 0.f;

    if (active) {
        const float n_man = expf(logn[r]);
        const float dx = lens[r], S = slp[r];
        const float wc = wcs[r], we = wes[r], dc = dcs[r], de = des[r];
        const float cE   = (2.0f / 3.0f) * de;
        // log2(cB), cB = (5/3)*sqrt(S)/n * dc^(2/3)
        const float l2cB = log2f(5.0f / 3.0f) + 0.5f * log2f(S) - log2f(n_man)
                         + (2.0f / 3.0f) * log2f(dc);
        negCE = -cE;
        kd = log2f(2.0f * dx) - l2cB;                            // K2 = ex2(-cE*lq + kd)
        xc = 1.0f - cE - we;                                      // e2 = Qref/(2 c W S dx)
        xd = -(log2f(2.0f * S * dx) + l2cB + log2f(wc));
        latp  = lat + r;
        lat_c = __ldg(latp);                     // t = 0
        lat_n = __ldg(latp + NREACH);            // t = 1
    }

    const int ITER = top ? (TSTEPS + 6) : (TSTEPS + 8);

    for (int i = 0; i < ITER; ++i) {
        const int t = i - skew;
        const int p = i & 1;
        const bool run = active && (t >= 0) && (t < TSTEPS);

        float lat_p = 0.f;
        if (run && (t + 2 < TSTEPS))
            lat_p = __ldg(latp + (size_t)(t + 2) * NREACH);     // depth-2 prefetch

        if (run) {
            float Inew = lat_c;
            if (has_par) {
                Inew += sq[p ^ 1][cbase + 2 * j] + sq[p ^ 1][cbase + 2 * j + 1];
            } else if (is_l8) {
                const int s = t & (DEPTH - 1);
                const unsigned* c0 = &g_ring[2 * j][s];
                const unsigned* c1 = &g_ring[2 * j + 1][s];
                unsigned v0 = ld_rlx(c0);
                while (v0 == SENT) { __nanosleep(32); v0 = ld_rlx(c0); }
                unsigned v1 = ld_rlx(c1);
                while (v1 == SENT) { __nanosleep(32); v1 = ld_rlx(c1); }
                st_rlx((unsigned*)c0, SENT);     // ack: slots free again
                st_rlx((unsigned*)c1, SENT);
                Inew += __uint_as_float(v0) + __uint_as_float(v1);
            }

            // ---- 4 Muskingum-Cunge substeps (3 MUFU each + rcp) ----
            float q = Q, io = Ip;
            #pragma unroll
            for (int s4 = 0; s4 < 4; ++s4) {
                const float Qref = fmaxf((Inew + io + q) * (1.0f / 3.0f), EPS_F);
                const float lq  = lg2f_(Qref);
                const float K2  = ex2f_(fmaf(negCE, lq, kd));    // 2K
                const float e2  = ex2f_(fmaf(xc, lq, xd));       // Qref/(2 c W S dx)
                const float X   = fmaxf(0.5f - e2, 0.0f);        // clip(.,0,.5); upper auto
                const float A   = K2 * X;                        // 2KX
                const float Bq  = K2 - A;                        // 2K(1-X)
                const float Dd  = Bq + DT_SUB_F;
                const float rD  = rcpf_(Dd);
                float acc = (DT_SUB_F - A) * Inew;
                acc = fmaf(DT_SUB_F + A, io, acc);
                acc = fmaf(Bq - DT_SUB_F, q, acc);
                q  = fmaxf(acc * rD, 0.0f);
                io = Inew;
            }
            Q = q; Ip = Inew;

            // ---- publish ----
            if (is_root) {
                unsigned* wp = &g_ring[b][t & (DEPTH - 1)];
                unsigned f = ld_rlx(wp);
                while (f != SENT) { __nanosleep(32); f = ld_rlx(wp); }
                st_rlx(wp, __float_as_uint(q));
            } else if (is_outlet) {
                out[t] = q;
            } else {
                sq[p][tid] = q;
            }

            lat_c = lat_n;
            lat_n = lat_p;
        }
        __syncthreads();
    }
}

extern "C" void kernel_launch(void* const* d_in, const int* in_sizes, int n_in,
                              void* d_out, int out_size) {
    const float* lat  = (const float*)d_in[0];
    const float* logn = (const float*)d_in[1];
    const float* lens = (const float*)d_in[2];
    const float* slp  = (const float*)d_in[3];
    const float* wcs  = (const float*)d_in[4];
    const float* wes  = (const float*)d_in[5];
    const float* dcs  = (const float*)d_in[6];
    const float* des  = (const float*)d_in[7];
    float* out = (float*)d_out;

    init_ring<<<1, 1024>>>();
    route_kernel<<<65, 256>>>(lat, logn, lens, slp, wcs, wes, dcs, des, out);
}

// round 6
// speedup vs baseline: 1.2877x; 1.2654x over previous
#include <cuda_runtime.h>

#define TSTEPS   2048
#define NREACH   16383
#define DEPTH    32
#define SENT     0xFFFFFFFFu
#define DT_SUB_F 21600.0f
#define EPS_F    1e-6f

// Ring: subtree-root (level 7, 64 elements) -> top CTA (level 8).
__device__ unsigned g_ring[64][DEPTH];

static __device__ __forceinline__ unsigned ld_rlx(const unsigned* p) {
    unsigned v;
    asm volatile("ld.relaxed.gpu.global.b32 %0, [%1];" : "=r"(v) : "l"(p) : "memory");
    return v;
}
static __device__ __forceinline__ void st_rlx(unsigned* p, unsigned v) {
    asm volatile("st.relaxed.gpu.global.b32 [%0], %1;" :: "l"(p), "r"(v) : "memory");
}
static __device__ __forceinline__ float ex2f_(float x){ float y; asm("ex2.approx.f32 %0, %1;" : "=f"(y) : "f"(x)); return y; }
static __device__ __forceinline__ float lg2f_(float x){ float y; asm("lg2.approx.f32 %0, %1;" : "=f"(y) : "f"(x)); return y; }
static __device__ __forceinline__ float rcpf_(float x){ float y; asm("rcp.approx.f32 %0, %1;" : "=f"(y) : "f"(x)); return y; }

// Bounded spin: fast pure-spin path, nanosleep only under pathological lag.
static __device__ __forceinline__ unsigned wait_data(const unsigned* p, unsigned v) {
    int tries = 0;
    while (v == SENT) {
        v = ld_rlx(p);
        if (++tries > 4096) __nanosleep(64);
    }
    return v;
}
static __device__ __forceinline__ void wait_free(unsigned* p, unsigned v) {
    int tries = 0;
    while (v != SENT) {
        v = ld_rlx(p);
        if (++tries > 4096) __nanosleep(64);
    }
}

__global__ void init_ring() {
    int i = blockIdx.x * blockDim.x + threadIdx.x;
    if (i < 64 * DEPTH) ((unsigned*)g_ring)[i] = SENT;
}

__global__ void __launch_bounds__(256, 1) route_kernel(
    const float* __restrict__ lat,
    const float* __restrict__ logn,
    const float* __restrict__ lens,
    const float* __restrict__ slp,
    const float* __restrict__ wcs,
    const float* __restrict__ wes,
    const float* __restrict__ dcs,
    const float* __restrict__ des,
    float* __restrict__ out)
{
    __shared__ float sq[2][256];

    const int b   = blockIdx.x;
    const int tid = threadIdx.x;
    const bool top = (b == 64);

    // ---- decode (level, element) ----
    int  j = 0, r = 0, skew = 0, cbase = 0;
    bool active = false, has_par = false, is_root = false, is_outlet = false, is_l8 = false;

    if (!top) {
        if (tid != 255) {
            const int u = 255 - tid;              // 1..255
            const int l = __clz(u) - 24;          // level 0..7 within subtree
            j = tid - (256 - (256 >> l));         // local element in level
            r = (16384 - (16384 >> l)) + b * (128 >> l) + j;
            skew    = l;
            active  = true;
            has_par = (l > 0);
            cbase   = (l > 0) ? (256 - (256 >> (l - 1))) : 0;
            is_root = (tid == 254);               // level-7 root of subtree
        }
    } else {
        if (tid < 63) {
            const int u  = 63 - tid;              // 1..63
            const int ll = __clz(u) - 26;         // 0..5 -> global level 8..13
            j = tid - (64 - (64 >> ll));
            const int lg = 8 + ll;
            r = (16384 - (16384 >> lg)) + j;
            skew    = ll;
            active  = true;
            has_par = (ll > 0);
            cbase   = (ll > 0) ? (64 - (64 >> (ll - 1))) : 0;
            is_l8   = (ll == 0);
            is_outlet = (ll == 5);
        }
    }

    // ---- per-reach constants (accurate one-time math) ----
    float negCE = 0.f, kd = 0.f, xc = 0.f, xd = 0.f;
    const float* latp = lat;
    float lat_c = 0.f, lat_n = 0.f, lat_n2 = 0.f;
    float Q = 0.f, Ip = 0.f;

    if (active) {
        const float n_man = expf(logn[r]);
        const float dx = lens[r], S = slp[r];
        const float wc = wcs[r], we = wes[r], dc = dcs[r], de = des[r];
        const float cE   = (2.0f / 3.0f) * de;
        // log2(cB), cB = (5/3)*sqrt(S)/n * dc^(2/3)
        const float l2cB = log2f(5.0f / 3.0f) + 0.5f * log2f(S) - log2f(n_man)
                         + (2.0f / 3.0f) * log2f(dc);
        negCE = -cE;
        kd = log2f(2.0f * dx) - l2cB;                            // K2 = ex2(-cE*lq + kd)
        xc = 1.0f - cE - we;                                      // e2 = Qref/(2 c W S dx)
        xd = -(log2f(2.0f * S * dx) + l2cB + log2f(wc));
        latp   = lat + r;
        lat_c  = __ldg(latp);                          // t = 0
        lat_n  = __ldg(latp + NREACH);                 // t = 1
        lat_n2 = __ldg(latp + 2 * (size_t)NREACH);     // t = 2
    }

    // Consumer prefetch state (top CTA, level-8 threads): loads for steps t, t+1
    // issued early; refilled 2 iterations ahead.
    unsigned pv0[2] = {SENT, SENT}, pv1[2] = {SENT, SENT};
    if (is_l8) {
        pv0[0] = ld_rlx(&g_ring[2 * j][0]);
        pv1[0] = ld_rlx(&g_ring[2 * j + 1][0]);
        pv0[1] = ld_rlx(&g_ring[2 * j][1]);
        pv1[1] = ld_rlx(&g_ring[2 * j + 1][1]);
    }

    const int ITER = top ? (TSTEPS + 6) : (TSTEPS + 8);

    for (int i = 0; i < ITER; ++i) {
        const int t = i - skew;
        const int p = i & 1;
        const bool run = active && (t >= 0) && (t < TSTEPS);

        float lat_p = 0.f;
        unsigned* wp = nullptr;
        unsigned vfree = SENT;
        if (run) {
            if (t + 3 < TSTEPS)
                lat_p = __ldg(latp + (size_t)(t + 3) * NREACH);  // depth-3 prefetch
            if (is_root) {                         // early-issue slot-free check
                wp = &g_ring[b][t & (DEPTH - 1)];
                vfree = ld_rlx(wp);
            }
        }

        if (run) {
            float Inew = lat_c;
            if (has_par) {
                Inew += sq[p ^ 1][cbase + 2 * j] + sq[p ^ 1][cbase + 2 * j + 1];
            } else if (is_l8) {
                const int s = t & (DEPTH - 1);
                unsigned* c0 = &g_ring[2 * j][s];
                unsigned* c1 = &g_ring[2 * j + 1][s];
                const unsigned v0 = wait_data(c0, pv0[t & 1]);   // usually hit by prefetch
                const unsigned v1 = wait_data(c1, pv1[t & 1]);
                st_rlx(c0, SENT);                 // ack: slots free again
                st_rlx(c1, SENT);
                Inew += __uint_as_float(v0) + __uint_as_float(v1);
                if (t + 2 < TSTEPS) {             // refill prefetch for t+2
                    const int s2 = (t + 2) & (DEPTH - 1);
                    pv0[t & 1] = ld_rlx(&g_ring[2 * j][s2]);
                    pv1[t & 1] = ld_rlx(&g_ring[2 * j + 1][s2]);
                }
            }

            // ---- 4 Muskingum-Cunge substeps (3 MUFU each + rcp) ----
            float q = Q, io = Ip;
            #pragma unroll
            for (int s4 = 0; s4 < 4; ++s4) {
                const float Qref = fmaxf((Inew + io + q) * (1.0f / 3.0f), EPS_F);
                const float lq  = lg2f_(Qref);
                const float K2  = ex2f_(fmaf(negCE, lq, kd));    // 2K
                const float e2  = ex2f_(fmaf(xc, lq, xd));       // Qref/(2 c W S dx)
                const float X   = fmaxf(0.5f - e2, 0.0f);        // clip(.,0,.5); upper auto
                const float A   = K2 * X;                        // 2KX
                const float Bq  = K2 - A;                        // 2K(1-X)
                const float Dd  = Bq + DT_SUB_F;
                const float rD  = rcpf_(Dd);
                float acc = (DT_SUB_F - A) * Inew;
                acc = fmaf(DT_SUB_F + A, io, acc);
                acc = fmaf(Bq - DT_SUB_F, q, acc);
                q  = fmaxf(acc * rD, 0.0f);
                io = Inew;
            }
            Q = q; Ip = Inew;

            // ---- publish ----
            if (is_root) {
                wait_free(wp, vfree);             // almost never spins (acks lag 32)
                st_rlx(wp, __float_as_uint(q));
            } else if (is_outlet) {
                out[t] = q;
            } else {
                sq[p][tid] = q;
            }

            lat_c  = lat_n;
            lat_n  = lat_n2;
            lat_n2 = lat_p;
        }
        __syncthreads();
    }
}

extern "C" void kernel_launch(void* const* d_in, const int* in_sizes, int n_in,
                              void* d_out, int out_size) {
    const float* lat  = (const float*)d_in[0];
    const float* logn = (const float*)d_in[1];
    const float* lens = (const float*)d_in[2];
    const float* slp  = (const float*)d_in[3];
    const float* wcs  = (const float*)d_in[4];
    const float* wes  = (const float*)d_in[5];
    const float* dcs  = (const float*)d_in[6];
    const float* des  = (const float*)d_in[7];
    float* out = (float*)d_out;

    init_ring<<<(64 * DEPTH + 255) / 256, 256>>>();
    route_kernel<<<65, 256>>>(lat, logn, lens, slp, wcs, wes, dcs, des, out);
}

// round 11
// speedup vs baseline: 2.0611x; 1.6006x over previous
#include <cuda_runtime.h>

#define TSTEPS   2048
#define NB       512              // 4-timestep blocks
#define NREACH   16383
#define RDEPTH   8                // ring depth in blocks
#define SENT     0xFFFFFFFFu
#define DT_SUB_F 21600.0f
#define EPS_F    1e-6f

// Ring: 64 subtree roots (level 7) -> top CTA (level 8). Per block: 4 words.
__device__ unsigned g_ring[64][RDEPTH][4];

static __device__ __forceinline__ unsigned ld_rlx(const unsigned* p) {
    unsigned v;
    asm volatile("ld.relaxed.gpu.global.b32 %0, [%1];" : "=r"(v) : "l"(p) : "memory");
    return v;
}
static __device__ __forceinline__ void st_rlx(unsigned* p, unsigned v) {
    asm volatile("st.relaxed.gpu.global.b32 [%0], %1;" :: "l"(p), "r"(v) : "memory");
}
static __device__ __forceinline__ float ex2f_(float x){ float y; asm("ex2.approx.f32 %0, %1;" : "=f"(y) : "f"(x)); return y; }
static __device__ __forceinline__ float lg2f_(float x){ float y; asm("lg2.approx.f32 %0, %1;" : "=f"(y) : "f"(x)); return y; }
static __device__ __forceinline__ float rcpf_(float x){ float y; asm("rcp.approx.f32 %0, %1;" : "=f"(y) : "f"(x)); return y; }

static __device__ __forceinline__ unsigned wait_data(const unsigned* p, unsigned v) {
    int tries = 0;
    while (v == SENT) {
        v = ld_rlx(p);
        if (++tries > 8192) __nanosleep(64);
    }
    return v;
}
static __device__ __forceinline__ void wait_free(unsigned* p, unsigned v) {
    int tries = 0;
    while (v != SENT) {
        v = ld_rlx(p);
        if (++tries > 8192) __nanosleep(64);
    }
}

__global__ void init_ring() {
    int i = blockIdx.x * blockDim.x + threadIdx.x;
    if (i < 64 * RDEPTH * 4) ((unsigned*)g_ring)[i] = SENT;
}

__global__ void __launch_bounds__(256, 1) route_kernel(
    const float* __restrict__ lat,
    const float* __restrict__ logn,
    const float* __restrict__ lens,
    const float* __restrict__ slp,
    const float* __restrict__ wcs,
    const float* __restrict__ wes,
    const float* __restrict__ dcs,
    const float* __restrict__ des,
    float* __restrict__ out)
{
    __shared__ float sq[2][4][256];     // [phase][k within block][thread]

    const int b   = blockIdx.x;
    const int tid = threadIdx.x;
    const bool top = (b == 64);

    // ---- decode (level, element) ----
    int  j = 0, r = 0, skew = 0, cbase = 0;
    bool active = false, has_par = false, is_root = false, is_outlet = false, is_l8 = false;

    if (!top) {
        if (tid != 255) {
            const int u = 255 - tid;              // 1..255
            const int l = __clz(u) - 24;          // level 0..7 within subtree
            j = tid - (256 - (256 >> l));
            r = (16384 - (16384 >> l)) + b * (128 >> l) + j;
            skew    = l;                          // in BLOCK units
            active  = true;
            has_par = (l > 0);
            cbase   = (l > 0) ? (256 - (256 >> (l - 1))) : 0;
            is_root = (tid == 254);
        }
    } else {
        if (tid < 63) {
            const int u  = 63 - tid;              // 1..63
            const int ll = __clz(u) - 26;         // 0..5 -> global level 8..13
            j = tid - (64 - (64 >> ll));
            const int lg = 8 + ll;
            r = (16384 - (16384 >> lg)) + j;
            skew    = ll;
            active  = true;
            has_par = (ll > 0);
            cbase   = (ll > 0) ? (64 - (64 >> (ll - 1))) : 0;
            is_l8   = (ll == 0);
            is_outlet = (ll == 5);
        }
    }

    // ---- per-reach constants ----
    float negCE = 0.f, kd = 0.f, xc = 0.f, xd = 0.f;
    const float* latp = lat;
    float Q = 0.f, Ip = 0.f;
    float lbuf[4] = {0.f, 0.f, 0.f, 0.f};

    if (active) {
        const float n_man = expf(logn[r]);
        const float dx = lens[r], S = slp[r];
        const float wc = wcs[r], we = wes[r], dc = dcs[r], de = des[r];
        const float cE   = (2.0f / 3.0f) * de;
        const float l2cB = log2f(5.0f / 3.0f) + 0.5f * log2f(S) - log2f(n_man)
                         + (2.0f / 3.0f) * log2f(dc);
        negCE = -cE;
        kd = log2f(2.0f * dx) - l2cB;             // 2K = ex2(-cE*lq + kd)
        xc = 1.0f - cE - we;                      // e2 = Qref/(2 c W S dx)
        xd = -(log2f(2.0f * S * dx) + l2cB + log2f(wc));
        latp = lat + r;
        if (skew == 0) {                          // preload block 0 (only skew-0 runs at bi=0)
            #pragma unroll
            for (int k = 0; k < 4; ++k)
                lbuf[k] = __ldg(latp + (size_t)k * NREACH);
        }
    }

    const int ITER = NB + 8;                      // covers max skew 7 (+1 slack)

    for (int bi = 0; bi < ITER; ++bi) {
        const int tb  = bi - skew;                // my block this iteration
        const int p   = bi & 1;
        const bool run = active && (tb >= 0) && (tb < NB);

        // ---- prefetch next block's lateral inflows (consumed next iteration) ----
        float ln[4] = {0.f, 0.f, 0.f, 0.f};
        {
            const int tbn = tb + 1;
            if (active && tbn >= 0 && tbn < NB) {
                const float* bp = latp + (size_t)(4 * tbn) * NREACH;
                #pragma unroll
                for (int k = 0; k < 4; ++k)
                    ln[k] = __ldg(bp + (size_t)k * NREACH);
            }
        }

        // ---- early-issue root slot-free checks (off critical path) ----
        unsigned vfree[4] = {SENT, SENT, SENT, SENT};
        unsigned* wslot = nullptr;
        if (run && is_root) {
            wslot = &g_ring[b][tb & (RDEPTH - 1)][0];
            #pragma unroll
            for (int k = 0; k < 4; ++k) vfree[k] = ld_rlx(wslot + k);
        }

        if (run) {
            // Level-8 threads: fetch both children's 4-word blocks from ring.
            float csum[4];
            if (is_l8) {
                const int s = tb & (RDEPTH - 1);
                unsigned* c0 = &g_ring[2 * j][s][0];
                unsigned* c1 = &g_ring[2 * j + 1][s][0];
                #pragma unroll
                for (int k = 0; k < 4; ++k) {
                    const unsigned v0 = wait_data(c0 + k, ld_rlx(c0 + k));
                    const unsigned v1 = wait_data(c1 + k, ld_rlx(c1 + k));
                    csum[k] = __uint_as_float(v0) + __uint_as_float(v1);
                }
                #pragma unroll
                for (int k = 0; k < 4; ++k) { st_rlx(c0 + k, SENT); st_rlx(c1 + k, SENT); }
            }

            float qk[4];
            #pragma unroll
            for (int k = 0; k < 4; ++k) {
                float Inew = lbuf[k];
                if (has_par)
                    Inew += sq[p ^ 1][k][cbase + 2 * j] + sq[p ^ 1][k][cbase + 2 * j + 1];
                else if (is_l8)
                    Inew += csum[k];

                // 4 Muskingum-Cunge substeps
                float q = Q, io = Ip;
                #pragma unroll
                for (int s4 = 0; s4 < 4; ++s4) {
                    const float Qref = fmaxf((Inew + io + q) * (1.0f / 3.0f), EPS_F);
                    const float lq  = lg2f_(Qref);
                    const float K2  = ex2f_(fmaf(negCE, lq, kd));    // 2K
                    const float e2  = ex2f_(fmaf(xc, lq, xd));       // Qref/(2cWSdx)
                    const float X   = fmaxf(0.5f - e2, 0.0f);
                    const float A   = K2 * X;
                    const float Bq  = K2 - A;
                    const float Dd  = Bq + DT_SUB_F;
                    const float rD  = rcpf_(Dd);
                    float acc = (DT_SUB_F - A) * Inew;
                    acc = fmaf(DT_SUB_F + A, io, acc);
                    acc = fmaf(Bq - DT_SUB_F, q, acc);
                    q  = fmaxf(acc * rD, 0.0f);
                    io = Inew;
                }
                Q = q; Ip = Inew;
                qk[k] = q;
            }

            // ---- publish ----
            if (is_root) {
                #pragma unroll
                for (int k = 0; k < 4; ++k) {
                    wait_free(wslot + k, vfree[k]);     // ring depth >> lead: rarely spins
                    st_rlx(wslot + k, __float_as_uint(qk[k]));
                }
            } else if (is_outlet) {
                #pragma unroll
                for (int k = 0; k < 4; ++k) out[4 * tb + k] = qk[k];
            } else {
                #pragma unroll
                for (int k = 0; k < 4; ++k) sq[p][k][tid] = qk[k];
            }
        }

        #pragma unroll
        for (int k = 0; k < 4; ++k) lbuf[k] = ln[k];

        __syncthreads();
    }
}

extern "C" void kernel_launch(void* const* d_in, const int* in_sizes, int n_in,
                              void* d_out, int out_size) {
    const float* lat  = (const float*)d_in[0];
    const float* logn = (const float*)d_in[1];
    const float* lens = (const float*)d_in[2];
    const float* slp  = (const float*)d_in[3];
    const float* wcs  = (const float*)d_in[4];
    const float* wes  = (const float*)d_in[5];
    const float* dcs  = (const float*)d_in[6];
    const float* des  = (const float*)d_in[7];
    float* out = (float*)d_out;

    init_ring<<<(64 * RDEPTH * 4 + 255) / 256, 256>>>();
    route_kernel<<<65, 256>>>(lat, logn, lens, slp, wcs, wes, dcs, des, out);
}

// round 12
// speedup vs baseline: 3.6121x; 1.7526x over previous
#include <cuda_runtime.h>

#define TSTEPS   2048
#define NB       512              // 4-timestep blocks
#define NREACH   16383
#define RDEPTH   8                // ring depth in blocks
#define SENT     0xFFFFFFFFu
#define DT_SUB_F 21600.0f
#define EPS_F    1e-6f

// Ring: 64 subtree roots (level 7) -> top CTA (level 8). One uint4 per block.
__device__ uint4 g_ring[64][RDEPTH];

static __device__ __forceinline__ uint4 ld_rlx4(const uint4* p) {
    uint4 v;
    asm volatile("ld.relaxed.gpu.global.v4.b32 {%0,%1,%2,%3}, [%4];"
                 : "=r"(v.x), "=r"(v.y), "=r"(v.z), "=r"(v.w) : "l"(p) : "memory");
    return v;
}
static __device__ __forceinline__ void st_rlx4(uint4* p, uint4 v) {
    asm volatile("st.relaxed.gpu.global.v4.b32 [%0], {%1,%2,%3,%4};"
                 :: "l"(p), "r"(v.x), "r"(v.y), "r"(v.z), "r"(v.w) : "memory");
}
static __device__ __forceinline__ bool any_sent(uint4 v) {
    return (v.x == SENT) | (v.y == SENT) | (v.z == SENT) | (v.w == SENT);
}
static __device__ __forceinline__ bool all_sent(uint4 v) {
    return (v.x == SENT) & (v.y == SENT) & (v.z == SENT) & (v.w == SENT);
}
static __device__ __forceinline__ uint4 wait_data4(const uint4* p, uint4 v) {
    int tries = 0;
    while (any_sent(v)) {
        v = ld_rlx4(p);
        if (++tries > 8192) __nanosleep(64);
    }
    return v;
}
static __device__ __forceinline__ void wait_free4(uint4* p, uint4 v) {
    int tries = 0;
    while (!all_sent(v)) {
        v = ld_rlx4(p);
        if (++tries > 8192) __nanosleep(64);
    }
}

static __device__ __forceinline__ float ex2f_(float x){ float y; asm("ex2.approx.f32 %0, %1;" : "=f"(y) : "f"(x)); return y; }
static __device__ __forceinline__ float lg2f_(float x){ float y; asm("lg2.approx.f32 %0, %1;" : "=f"(y) : "f"(x)); return y; }
static __device__ __forceinline__ float rcpf_(float x){ float y; asm("rcp.approx.f32 %0, %1;" : "=f"(y) : "f"(x)); return y; }

__global__ void init_ring() {
    int i = blockIdx.x * blockDim.x + threadIdx.x;
    if (i < 64 * RDEPTH * 4) ((unsigned*)g_ring)[i] = SENT;
}

__global__ void __launch_bounds__(256, 1) route_kernel(
    const float* __restrict__ lat,
    const float* __restrict__ logn,
    const float* __restrict__ lens,
    const float* __restrict__ slp,
    const float* __restrict__ wcs,
    const float* __restrict__ wes,
    const float* __restrict__ dcs,
    const float* __restrict__ des,
    float* __restrict__ out)
{
    __shared__ float sq[2][4][256];     // [phase][k within block][thread]

    const int b   = blockIdx.x;
    const int tid = threadIdx.x;
    const bool top = (b == 64);

    // ---- decode (level, element) ----
    int  j = 0, r = 0, skew = 0, cbase = 0;
    bool active = false, has_par = false, is_root = false, is_outlet = false, is_l8 = false;

    if (!top) {
        if (tid != 255) {
            const int u = 255 - tid;              // 1..255
            const int l = __clz(u) - 24;          // level 0..7 within subtree
            j = tid - (256 - (256 >> l));
            r = (16384 - (16384 >> l)) + b * (128 >> l) + j;
            skew    = l;                          // in BLOCK units
            active  = true;
            has_par = (l > 0);
            cbase   = (l > 0) ? (256 - (256 >> (l - 1))) : 0;
            is_root = (tid == 254);
        }
    } else {
        if (tid < 63) {
            const int u  = 63 - tid;              // 1..63
            const int ll = __clz(u) - 26;         // 0..5 -> global level 8..13
            j = tid - (64 - (64 >> ll));
            const int lg = 8 + ll;
            r = (16384 - (16384 >> lg)) + j;
            skew    = ll;
            active  = true;
            has_par = (ll > 0);
            cbase   = (ll > 0) ? (64 - (64 >> (ll - 1))) : 0;
            is_l8   = (ll == 0);
            is_outlet = (ll == 5);
        }
    }

    // ---- per-reach constants ----
    float negCE = 0.f, kd = 0.f, xc = 0.f, xd = 0.f;
    const float* latp = lat;
    float Q = 0.f, Ip = 0.f;
    float lbuf[4] = {0.f, 0.f, 0.f, 0.f};

    if (active) {
        const float n_man = expf(logn[r]);
        const float dx = lens[r], S = slp[r];
        const float wc = wcs[r], we = wes[r], dc = dcs[r], de = des[r];
        const float cE   = (2.0f / 3.0f) * de;
        const float l2cB = log2f(5.0f / 3.0f) + 0.5f * log2f(S) - log2f(n_man)
                         + (2.0f / 3.0f) * log2f(dc);
        negCE = -cE;
        kd = log2f(2.0f * dx) - l2cB;             // 2K = ex2(-cE*lq + kd)
        xc = 1.0f - cE - we;                      // e2 = Qref/(2 c W S dx)
        xd = -(log2f(2.0f * S * dx) + l2cB + log2f(wc));
        latp = lat + r;
        if (skew == 0) {                          // preload block 0
            #pragma unroll
            for (int k = 0; k < 4; ++k)
                lbuf[k] = __ldg(latp + (size_t)k * NREACH);
        }
    }

    // Consumer prefetch state (top CTA level-8 threads): block 0's ring data.
    uint4 pv0 = {SENT, SENT, SENT, SENT}, pv1 = pv0;
    if (is_l8) {
        pv0 = ld_rlx4(&g_ring[2 * j][0]);
        pv1 = ld_rlx4(&g_ring[2 * j + 1][0]);
    }
    const uint4 SENT4 = {SENT, SENT, SENT, SENT};

    const int ITER = NB + 8;

    for (int bi = 0; bi < ITER; ++bi) {
        const int tb  = bi - skew;
        const int p   = bi & 1;
        const bool run = active && (tb >= 0) && (tb < NB);

        // ---- prefetch next block's lateral inflows ----
        float ln[4] = {0.f, 0.f, 0.f, 0.f};
        {
            const int tbn = tb + 1;
            if (active && tbn >= 0 && tbn < NB) {
                const float* bp = latp + (size_t)(4 * tbn) * NREACH;
                #pragma unroll
                for (int k = 0; k < 4; ++k)
                    ln[k] = __ldg(bp + (size_t)k * NREACH);
            }
        }

        // ---- early-issue root slot-free check (one v4 load) ----
        uint4 vfree = SENT4;
        uint4* wslot = nullptr;
        if (run && is_root) {
            wslot = &g_ring[b][tb & (RDEPTH - 1)];
            vfree = ld_rlx4(wslot);
        }

        if (run) {
            // Level-8: consume both children's blocks (usually satisfied by prefetch).
            float csum[4];
            if (is_l8) {
                const int s = tb & (RDEPTH - 1);
                uint4* c0 = &g_ring[2 * j][s];
                uint4* c1 = &g_ring[2 * j + 1][s];
                const uint4 v0 = wait_data4(c0, pv0);
                const uint4 v1 = wait_data4(c1, pv1);
                st_rlx4(c0, SENT4);               // ack
                st_rlx4(c1, SENT4);
                csum[0] = __uint_as_float(v0.x) + __uint_as_float(v1.x);
                csum[1] = __uint_as_float(v0.y) + __uint_as_float(v1.y);
                csum[2] = __uint_as_float(v0.z) + __uint_as_float(v1.z);
                csum[3] = __uint_as_float(v0.w) + __uint_as_float(v1.w);
                if (tb + 1 < NB) {                // prefetch next block's payloads
                    const int s2 = (tb + 1) & (RDEPTH - 1);
                    pv0 = ld_rlx4(&g_ring[2 * j][s2]);
                    pv1 = ld_rlx4(&g_ring[2 * j + 1][s2]);
                }
            }

            float qk[4];
            #pragma unroll
            for (int k = 0; k < 4; ++k) {
                float Inew = lbuf[k];
                if (has_par)
                    Inew += sq[p ^ 1][k][cbase + 2 * j] + sq[p ^ 1][k][cbase + 2 * j + 1];
                else if (is_l8)
                    Inew += csum[k];

                // 4 Muskingum-Cunge substeps
                float q = Q, io = Ip;
                #pragma unroll
                for (int s4 = 0; s4 < 4; ++s4) {
                    const float Qref = fmaxf((Inew + io + q) * (1.0f / 3.0f), EPS_F);
                    const float lq  = lg2f_(Qref);
                    const float K2  = ex2f_(fmaf(negCE, lq, kd));    // 2K
                    const float e2  = ex2f_(fmaf(xc, lq, xd));       // Qref/(2cWSdx)
                    const float X   = fmaxf(0.5f - e2, 0.0f);
                    const float A   = K2 * X;
                    const float Bq  = K2 - A;
                    const float Dd  = Bq + DT_SUB_F;
                    const float rD  = rcpf_(Dd);
                    float acc = (DT_SUB_F - A) * Inew;
                    acc = fmaf(DT_SUB_F + A, io, acc);
                    acc = fmaf(Bq - DT_SUB_F, q, acc);
                    q  = fmaxf(acc * rD, 0.0f);
                    io = Inew;
                }
                Q = q; Ip = Inew;
                qk[k] = q;
            }

            // ---- publish ----
            if (is_root) {
                wait_free4(wslot, vfree);         // rarely spins (lead << RDEPTH)
                uint4 pay;
                pay.x = __float_as_uint(qk[0]);
                pay.y = __float_as_uint(qk[1]);
                pay.z = __float_as_uint(qk[2]);
                pay.w = __float_as_uint(qk[3]);
                st_rlx4(wslot, pay);
            } else if (is_outlet) {
                #pragma unroll
                for (int k = 0; k < 4; ++k) out[4 * tb + k] = qk[k];
            } else {
                #pragma unroll
                for (int k = 0; k < 4; ++k) sq[p][k][tid] = qk[k];
            }
        }

        #pragma unroll
        for (int k = 0; k < 4; ++k) lbuf[k] = ln[k];

        __syncthreads();
    }
}

extern "C" void kernel_launch(void* const* d_in, const int* in_sizes, int n_in,
                              void* d_out, int out_size) {
    const float* lat  = (const float*)d_in[0];
    const float* logn = (const float*)d_in[1];
    const float* lens = (const float*)d_in[2];
    const float* slp  = (const float*)d_in[3];
    const float* wcs  = (const float*)d_in[4];
    const float* wes  = (const float*)d_in[5];
    const float* dcs  = (const float*)d_in[6];
    const float* des  = (const float*)d_in[7];
    float* out = (float*)d_out;

    init_ring<<<(64 * RDEPTH * 4 + 255) / 256, 256>>>();
    route_kernel<<<65, 256>>>(lat, logn, lens, slp, wcs, wes, dcs, des, out);
}